// round 15
// baseline (speedup 1.0000x reference)
#include <cuda_runtime.h>

#define SEQ   1024
#define BATCH 32
#define DH    512
#define DIN   512
#define NCTA  128

typedef unsigned long long ull;

// ---------------- scratch (device globals; no allocations allowed) ----------
__device__ float g_gates[(size_t)SEQ * BATCH * 4 * DH]; // [t][b][g][h]
__device__ float g_Wt[4 * DH * DH];                     // [g][h][k] transposed recurrent weights
__device__ float g_H[2][2][BATCH * DH];                 // [pingpong][big/small] in A-fragment layout
__device__ unsigned g_flags[NCTA * 32];                 // per-CTA step flags, 128B apart
__device__ unsigned g_gchunk[8 * 32];                   // gate-chunk completion counters, 128B apart

__device__ __forceinline__ unsigned tf32cvt(float x) {
    unsigned u;
    asm("cvt.rna.tf32.f32 %0, %1;" : "=r"(u) : "f"(x));
    return u;
}

__device__ __forceinline__ float frcp(float x) {
    float r;
    asm("rcp.approx.f32 %0, %1;" : "=f"(r) : "f"(x));
    return r;
}

// ---------------- init ------------------------------------------------------
__global__ void k_init() {
    int i = blockIdx.x * blockDim.x + threadIdx.x;
    if (i < NCTA * 32) g_flags[i] = 0;
    if (i < 8 * 32) g_gchunk[i] = 0;
    if (i < 2 * 2 * BATCH * DH) ((float*)g_H)[i] = 0.f;
}

// ---------------- transpose recurrent weights:  Wt[g][h][k] = Wh_g[k][h] ----
__global__ void k_transpose(const float* __restrict__ W0, const float* __restrict__ W1,
                            const float* __restrict__ W2, const float* __restrict__ W3) {
    __shared__ float tile[32][33];
    int gz = blockIdx.z;
    const float* W = (gz == 0) ? W0 : (gz == 1) ? W1 : (gz == 2) ? W2 : W3;
    int h0 = blockIdx.x * 32;
    int k0 = blockIdx.y * 32;
    for (int r = threadIdx.y; r < 32; r += 8)
        tile[r][threadIdx.x] = W[(size_t)(k0 + r) * DH + h0 + threadIdx.x];
    __syncthreads();
    float* out = g_Wt + (size_t)gz * DH * DH;
    for (int r = threadIdx.y; r < 32; r += 8)
        out[(size_t)(h0 + r) * DH + k0 + threadIdx.x] = tile[threadIdx.x][r];
}

// ---------------- phase 1: input projections, tf32 tensor-core GEMM ---------
// mode 0 (lead):  gridDim.y=64,  t-chunks {0,1}:  tc=by&1,      b=by>>1
// mode 1 (rest):  gridDim.y=192, t-chunks {2..7}: tc=2+(by>>5), b=by&31
//                 chunk-major; publishes g_gchunk[tc] per CTA completion.
#define ASTRIDE 20
#define BSTRIDE 136

__global__ __launch_bounds__(256, 1) void k_xproj(
    const float* __restrict__ x,
    const float* __restrict__ Wi, const float* __restrict__ Wf,
    const float* __restrict__ Wo, const float* __restrict__ Wc,
    const float* __restrict__ bi, const float* __restrict__ bf,
    const float* __restrict__ bo, const float* __restrict__ bc,
    int mode)
{
    __shared__ unsigned As[128 * ASTRIDE];
    __shared__ unsigned Bs[16 * BSTRIDE];

    int tid = threadIdx.x;
    int warp = tid >> 5, lane = tid & 31;
    int wm = warp >> 1, wn = warp & 1;
    int grp = lane >> 2, tg = lane & 3;

    int by = blockIdx.y;
    int tc, bb;
    if (mode == 0) { tc = by & 1;        bb = by >> 1; }
    else           { tc = 2 + (by >> 5); bb = by & 31; }
    int m0 = (bb * 8 + tc) * 128;

    int n0 = blockIdx.x * 128;
    int g = n0 >> 9;
    int nn0 = n0 & 511;
    const float* W    = (g == 0) ? Wi : (g == 1) ? Wf : (g == 2) ? Wo : Wc;
    const float* bias = (g == 0) ? bi : (g == 1) ? bf : (g == 2) ? bo : bc;

    float c[2][8][4];
#pragma unroll
    for (int i = 0; i < 2; i++)
#pragma unroll
        for (int j = 0; j < 8; j++)
#pragma unroll
            for (int q = 0; q < 4; q++) c[i][j][q] = 0.f;

    int arow[2], ac4[2], bk[2], bnq[2];
#pragma unroll
    for (int u = 0; u < 2; u++) {
        int ci = tid + u * 256;
        arow[u] = ci >> 2;  ac4[u] = ci & 3;
        bk[u]   = ci >> 5;  bnq[u] = ci & 31;
    }

    float4 pa[2], pb[2];
#pragma unroll
    for (int u = 0; u < 2; u++) {
        pa[u] = *(const float4*)(x + (size_t)(m0 + arow[u]) * DIN + ac4[u] * 4);
        pb[u] = *(const float4*)(W + (size_t)bk[u] * DH + nn0 + bnq[u] * 4);
    }

    for (int kt = 0; kt < DIN; kt += 16) {
        __syncthreads();
#pragma unroll
        for (int u = 0; u < 2; u++) {
            unsigned* pA = &As[arow[u] * ASTRIDE + ac4[u] * 4];
            pA[0] = tf32cvt(pa[u].x); pA[1] = tf32cvt(pa[u].y);
            pA[2] = tf32cvt(pa[u].z); pA[3] = tf32cvt(pa[u].w);
            unsigned* pB = &Bs[bk[u] * BSTRIDE + bnq[u] * 4];
            pB[0] = tf32cvt(pb[u].x); pB[1] = tf32cvt(pb[u].y);
            pB[2] = tf32cvt(pb[u].z); pB[3] = tf32cvt(pb[u].w);
        }
        __syncthreads();
        if (kt + 16 < DIN) {
#pragma unroll
            for (int u = 0; u < 2; u++) {
                pa[u] = *(const float4*)(x + (size_t)(m0 + arow[u]) * DIN + kt + 16 + ac4[u] * 4);
                pb[u] = *(const float4*)(W + (size_t)(kt + 16 + bk[u]) * DH + nn0 + bnq[u] * 4);
            }
        }
#pragma unroll
        for (int kk = 0; kk < 16; kk += 8) {
            unsigned a[2][4], b[8][2];
#pragma unroll
            for (int mf = 0; mf < 2; mf++) {
                int rb = wm * 32 + mf * 16 + grp;
                a[mf][0] = As[rb * ASTRIDE + kk + tg];
                a[mf][1] = As[(rb + 8) * ASTRIDE + kk + tg];
                a[mf][2] = As[rb * ASTRIDE + kk + tg + 4];
                a[mf][3] = As[(rb + 8) * ASTRIDE + kk + tg + 4];
            }
#pragma unroll
            for (int nf = 0; nf < 8; nf++) {
                int cb = wn * 64 + nf * 8 + grp;
                b[nf][0] = Bs[(kk + tg) * BSTRIDE + cb];
                b[nf][1] = Bs[(kk + tg + 4) * BSTRIDE + cb];
            }
#pragma unroll
            for (int mf = 0; mf < 2; mf++)
#pragma unroll
                for (int nf = 0; nf < 8; nf++) {
                    asm volatile(
                        "mma.sync.aligned.m16n8k8.row.col.f32.tf32.tf32.f32 "
                        "{%0,%1,%2,%3}, {%4,%5,%6,%7}, {%8,%9}, {%0,%1,%2,%3};"
                        : "+f"(c[mf][nf][0]), "+f"(c[mf][nf][1]),
                          "+f"(c[mf][nf][2]), "+f"(c[mf][nf][3])
                        : "r"(a[mf][0]), "r"(a[mf][1]), "r"(a[mf][2]), "r"(a[mf][3]),
                          "r"(b[nf][0]), "r"(b[nf][1]));
                }
        }
    }

#pragma unroll
    for (int mf = 0; mf < 2; mf++) {
        int row0 = m0 + wm * 32 + mf * 16 + grp;
#pragma unroll
        for (int nf = 0; nf < 8; nf++) {
            int h = nn0 + wn * 64 + nf * 8 + tg * 2;
            float2 bb2 = *(const float2*)(bias + h);
            {
                int b = row0 >> 10, t = row0 & 1023;
                float2 v = make_float2(c[mf][nf][0] + bb2.x, c[mf][nf][1] + bb2.y);
                *(float2*)(g_gates + ((size_t)(t * BATCH + b) * 4 + g) * DH + h) = v;
            }
            {
                int r1 = row0 + 8;
                int b = r1 >> 10, t = r1 & 1023;
                float2 v = make_float2(c[mf][nf][2] + bb2.x, c[mf][nf][3] + bb2.y);
                *(float2*)(g_gates + ((size_t)(t * BATCH + b) * 4 + g) * DH + h) = v;
            }
        }
    }

    // rest-mode: publish chunk completion (512 CTAs per chunk)
    if (mode == 1) {
        __syncthreads();
        if (tid == 0) {
            __threadfence();
            atomicAdd(&g_gchunk[tc * 32], 1u);
        }
    }
}

// ---------------- phase 2: persistent recurrence, tensor-core ---------------
// EXACT R14 structure + per-chunk gate-ready gate (poll once per 128 steps).
#define STEP_THREADS 512
#define RS 24
#define SMEM_STEPS (16 * 32 * RS * 4)

#define MMA_T(C, A, B)                                                          \
    asm volatile(                                                               \
        "mma.sync.aligned.m16n8k8.row.col.f32.tf32.tf32.f32 "                   \
        "{%0,%1,%2,%3}, {%4,%5,%6,%7}, {%8,%9}, {%0,%1,%2,%3};"                 \
        : "+f"(C[0]), "+f"(C[1]), "+f"(C[2]), "+f"(C[3])                        \
        : "r"(A[0]), "r"(A[1]), "r"(A[2]), "r"(A[3]), "r"(B[0]), "r"(B[1]));

__global__ __launch_bounds__(STEP_THREADS, 1) void k_steps(float* __restrict__ out) {
    extern __shared__ float red[];   // [ws][m(32)][RS], n in [0,16)

    int tid = threadIdx.x;
    int lane = tid & 31;
    int ws = tid >> 5;
    int grp = lane >> 2, tg = lane & 3;
    int bx = blockIdx.x;

    // ---- precompute W fragments (big + small), resident all steps ----------
    unsigned wb[2][4][2], wsm[2][4][2];
#pragma unroll
    for (int nt = 0; nt < 2; nt++) {
        int n = nt * 8 + grp;
        int g = n >> 2, h2 = n & 3;
        const float* wrow = g_Wt + (size_t)g * DH * DH + (size_t)(bx * 4 + h2) * DH;
#pragma unroll
        for (int q = 0; q < 4; q++) {
            int k0 = 32 * ws + 8 * q + tg;
#pragma unroll
            for (int u = 0; u < 2; u++) {
                float w = wrow[k0 + u * 4];
                unsigned b = tf32cvt(w);
                wb[nt][q][u] = b;
                wsm[nt][q][u] = tf32cvt(w - __uint_as_float(b));
            }
        }
    }

    // every lane polls one of this warp's 8 producer flags (CTAs 8*ws..8*ws+7)
    const unsigned* myflag = &g_flags[(ws * 8 + (lane & 7)) * 32];

    // per-thread reduction/epilogue identity: (m, n)
    int m_r = tid >> 4;
    int n_r = tid & 15;
    const float* gsrc = g_gates + ((size_t)m_r * 4 + (n_r >> 2)) * DH + bx * 4 + (n_r & 3);

    // leader (n_r < 4) H-write index in fragment layout
    int hg_e = bx * 4 + n_r;                 // n_r = h2 for leaders
    int mtE = m_r >> 4, mmE = m_r & 15;
    int grpE = mmE & 7, mhighE = mmE >> 3;
    int K8E = hg_e >> 3, kkE = hg_e & 7;
    int tgE = kkE & 3, khighE = kkE >> 2;
    int idxE = (((K8E * 2 + mtE) * 32) + grpE * 4 + tgE) * 4 + (khighE * 2 + mhighE);
    float Creg = 0.f;

    int next_chunk = 2;

    for (int t = 0; t < SEQ; t++) {
        // ---- once per 128 steps: confirm the next gate chunk is produced ----
        if (t == (next_chunk << 7) && next_chunk < 8) {
            const unsigned* cf = &g_gchunk[next_chunk * 32];
            unsigned v;
            do {
                asm volatile("ld.acquire.gpu.global.u32 %0, [%1];"
                             : "=r"(v) : "l"(cf) : "memory");
            } while (v < 512u);
            next_chunk++;
        }

        // ---- prefetch this thread's gate pre-activation (DRAM, overlaps wait)
        float gv = __ldg(gsrc + (size_t)t * BATCH * 4 * DH);

        // ---- wait for this warp's 8 producers (skip t=0: H0 preset to 0) ----
        if (t > 0) {
            unsigned target = (unsigned)t;
            unsigned v;
            do {
                asm volatile("ld.acquire.gpu.global.u32 %0, [%1];"
                             : "=r"(v) : "l"(myflag) : "memory");
            } while (v < target);
            __syncwarp();
        }

        // ---- tensor-core compute: C[2][2][4] over K=32, pre-split H --------
        const float* Hb = g_H[t & 1][0];
        const float* Hs = g_H[t & 1][1];
        float c[2][2][4];
#pragma unroll
        for (int i = 0; i < 2; i++)
#pragma unroll
            for (int j = 0; j < 2; j++)
#pragma unroll
                for (int q = 0; q < 4; q++) c[i][j][q] = 0.f;

#pragma unroll
        for (int q = 0; q < 4; q++) {
            int K8 = ws * 4 + q;
#pragma unroll
            for (int mt = 0; mt < 2; mt++) {
                size_t off = ((size_t)(K8 * 2 + mt) * 32 + lane) * 4;
                unsigned ab[4], as_[4];
                asm("ld.global.cg.v4.b32 {%0,%1,%2,%3}, [%4];"
                    : "=r"(ab[0]), "=r"(ab[1]), "=r"(ab[2]), "=r"(ab[3])
                    : "l"(Hb + off));
                asm("ld.global.cg.v4.b32 {%0,%1,%2,%3}, [%4];"
                    : "=r"(as_[0]), "=r"(as_[1]), "=r"(as_[2]), "=r"(as_[3])
                    : "l"(Hs + off));
#pragma unroll
                for (int nt = 0; nt < 2; nt++) {
                    MMA_T(c[mt][nt], ab,  wb[nt][q]);
                    MMA_T(c[mt][nt], ab,  wsm[nt][q]);
                    MMA_T(c[mt][nt], as_, wb[nt][q]);
                }
            }
        }

        // ---- store partials to red[ws][m][n] ----
#pragma unroll
        for (int mt = 0; mt < 2; mt++)
#pragma unroll
            for (int nt = 0; nt < 2; nt++) {
                float* r0 = &red[((ws * 32) + 16 * mt + grp) * RS + nt * 8 + 2 * tg];
                *(float2*)r0            = make_float2(c[mt][nt][0], c[mt][nt][1]);
                *(float2*)(r0 + 8 * RS) = make_float2(c[mt][nt][2], c[mt][nt][3]);
            }
        __syncthreads();

        // ---- 16-way k-split reduction (all 512 threads, one (m,n) each) ----
        float s0 = gv, s1 = 0.f, s2 = 0.f, s3 = 0.f;
        {
            const float* rp = &red[m_r * RS + n_r];
#pragma unroll
            for (int w4 = 0; w4 < 4; w4++) {
                s0 += rp[(w4 * 4 + 0) * 32 * RS];
                s1 += rp[(w4 * 4 + 1) * 32 * RS];
                s2 += rp[(w4 * 4 + 2) * 32 * RS];
                s3 += rp[(w4 * 4 + 3) * 32 * RS];
            }
        }
        float s = (s0 + s1) + (s2 + s3);

        // gather the 4 gate sums to leaders (n_r < 4) via shfl
        float v1 = __shfl_sync(0xffffffffu, s, lane + 4);
        float v2 = __shfl_sync(0xffffffffu, s, lane + 8);
        float v3 = __shfl_sync(0xffffffffu, s, lane + 12);

        float Hn = 0.f;
        if (n_r < 4) {
            float I  = frcp(1.f + __expf(-s));
            float F  = frcp(1.f + __expf(-v1));
            float O  = frcp(1.f + __expf(-v2));
            float e2 = __expf(2.f * v3);
            float Cc = 1.f - 2.f * frcp(e2 + 1.f);     // tanh

            Creg = F * Creg + I * Cc;
            float ec = __expf(2.f * Creg);
            Hn = O * (1.f - 2.f * frcp(ec + 1.f));

            // pre-split store for next step's consumers
            unsigned hb = tf32cvt(Hn);
            float hbf = __uint_as_float(hb);
            float hsf = __uint_as_float(tf32cvt(Hn - hbf));
            int p = (t + 1) & 1;
            __stcg(&g_H[p][0][idxE], hbf);
            __stcg(&g_H[p][1][idxE], hsf);
        }
        __syncthreads();

        // ---- publish: release store of this CTA's flag ----
        if (tid == 0) {
            asm volatile("st.release.gpu.global.u32 [%0], %1;"
                         :: "l"(&g_flags[bx * 32]), "r"((unsigned)(t + 1)) : "memory");
        }
        if (n_r < 4)
            out[((size_t)m_r * SEQ + t) * DH + hg_e] = Hn;
    }
}

// ---------------- final H copy ---------------------------------------------
__global__ void k_final(float* __restrict__ out) {
    int i = blockIdx.x * blockDim.x + threadIdx.x;
    if (i < BATCH * DH) {
        int m = i >> 9, h = i & 511;
        int mt = m >> 4, mm = m & 15;
        int grp = mm & 7, mhigh = mm >> 3;
        int K8 = h >> 3, kk = h & 7;
        int tg = kk & 3, khigh = kk >> 2;
        int idx = (((K8 * 2 + mt) * 32) + grp * 4 + tg) * 4 + (khigh * 2 + mhigh);
        out[(size_t)BATCH * SEQ * DH + i] = g_H[0][0][idx] + g_H[0][1][idx];
    }
}

// ---------------- launch ----------------------------------------------------
extern "C" void kernel_launch(void* const* d_in, const int* in_sizes, int n_in,
                              void* d_out, int out_size) {
    const float* x   = (const float*)d_in[0];
    const float* Wxi = (const float*)d_in[1];
    const float* Whi = (const float*)d_in[2];
    const float* bi  = (const float*)d_in[3];
    const float* Wxf = (const float*)d_in[4];
    const float* Whf = (const float*)d_in[5];
    const float* bf  = (const float*)d_in[6];
    const float* Wxo = (const float*)d_in[7];
    const float* Who = (const float*)d_in[8];
    const float* bo  = (const float*)d_in[9];
    const float* Wxc = (const float*)d_in[10];
    const float* Whc = (const float*)d_in[11];
    const float* bc  = (const float*)d_in[12];
    float* out = (float*)d_out;

    static int inited = 0;
    static cudaStream_t s2;
    static cudaEvent_t e_fork, e_join;
    if (!inited) {
        cudaFuncSetAttribute(k_steps, cudaFuncAttributeMaxDynamicSharedMemorySize, SMEM_STEPS);
        int leastPrio, greatestPrio;
        cudaDeviceGetStreamPriorityRange(&leastPrio, &greatestPrio);
        cudaStreamCreateWithPriority(&s2, cudaStreamNonBlocking, leastPrio);
        cudaEventCreateWithFlags(&e_fork, cudaEventDisableTiming);
        cudaEventCreateWithFlags(&e_join, cudaEventDisableTiming);
        inited = 1;
    }

    k_init<<<256, 256>>>();
    k_transpose<<<dim3(16, 16, 4), dim3(32, 8)>>>(Whi, Whf, Who, Whc);
    // lead: gate chunks 0-1 (sequential, before k_steps)
    k_xproj<<<dim3(16, 64), 256>>>(x, Wxi, Wxf, Wxo, Wxc, bi, bf, bo, bc, 0);
    // fork: rest (chunks 2-7) on low-priority stream, concurrent with k_steps
    cudaEventRecord(e_fork, 0);
    cudaStreamWaitEvent(s2, e_fork, 0);
    k_xproj<<<dim3(16, 192), 256, 0, s2>>>(x, Wxi, Wxf, Wxo, Wxc, bi, bf, bo, bc, 1);
    cudaEventRecord(e_join, s2);
    // recurrence (consumes chunks as they complete)
    k_steps<<<NCTA, STEP_THREADS, SMEM_STEPS>>>(out);
    // join side stream back before the final node
    cudaStreamWaitEvent(0, e_join, 0);
    k_final<<<64, 256>>>(out);
}

// round 16
// speedup vs baseline: 1.0851x; 1.0851x over previous
#include <cuda_runtime.h>

#define SEQ   1024
#define BATCH 32
#define DH    512
#define DIN   512
#define NCTA  128

typedef unsigned long long ull;

// ---------------- scratch (device globals; no allocations allowed) ----------
__device__ float g_gates[(size_t)SEQ * BATCH * 4 * DH]; // [t][b][g][h]
__device__ float g_Wt[4 * DH * DH];                     // [g][h][k] transposed recurrent weights
__device__ float g_H[2][2][BATCH * DH];                 // [pingpong][big/small] in A-fragment layout
__device__ unsigned g_flags[NCTA * 32];                 // per-CTA step flags, 128B apart

__device__ __forceinline__ unsigned tf32cvt(float x) {
    unsigned u;
    asm("cvt.rna.tf32.f32 %0, %1;" : "=r"(u) : "f"(x));
    return u;
}

__device__ __forceinline__ float frcp(float x) {
    float r;
    asm("rcp.approx.f32 %0, %1;" : "=f"(r) : "f"(x));
    return r;
}

// ---------------- init ------------------------------------------------------
__global__ void k_init() {
    int i = blockIdx.x * blockDim.x + threadIdx.x;
    if (i < NCTA * 32) g_flags[i] = 0;
    if (i < 2 * 2 * BATCH * DH) ((float*)g_H)[i] = 0.f;
}

// ---------------- transpose recurrent weights:  Wt[g][h][k] = Wh_g[k][h] ----
__global__ void k_transpose(const float* __restrict__ W0, const float* __restrict__ W1,
                            const float* __restrict__ W2, const float* __restrict__ W3) {
    __shared__ float tile[32][33];
    int gz = blockIdx.z;
    const float* W = (gz == 0) ? W0 : (gz == 1) ? W1 : (gz == 2) ? W2 : W3;
    int h0 = blockIdx.x * 32;
    int k0 = blockIdx.y * 32;
    for (int r = threadIdx.y; r < 32; r += 8)
        tile[r][threadIdx.x] = W[(size_t)(k0 + r) * DH + h0 + threadIdx.x];
    __syncthreads();
    float* out = g_Wt + (size_t)gz * DH * DH;
    for (int r = threadIdx.y; r < 32; r += 8)
        out[(size_t)(h0 + r) * DH + k0 + threadIdx.x] = tile[threadIdx.x][r];
}

// ---------------- phase 1: input projections, tf32 tensor-core GEMM ---------
// __launch_bounds__(256, 2): cap regs at 128 so TWO CTAs co-reside per SM
// (R15 ncu: occ 12.1% @156 regs was the xproj bottleneck, tensor only 33.5%).
#define ASTRIDE 20
#define BSTRIDE 136

__global__ __launch_bounds__(256, 2) void k_xproj(
    const float* __restrict__ x,
    const float* __restrict__ Wi, const float* __restrict__ Wf,
    const float* __restrict__ Wo, const float* __restrict__ Wc,
    const float* __restrict__ bi, const float* __restrict__ bf,
    const float* __restrict__ bo, const float* __restrict__ bc)
{
    __shared__ unsigned As[128 * ASTRIDE];
    __shared__ unsigned Bs[16 * BSTRIDE];

    int tid = threadIdx.x;
    int warp = tid >> 5, lane = tid & 31;
    int wm = warp >> 1, wn = warp & 1;
    int grp = lane >> 2, tg = lane & 3;

    int m0 = blockIdx.y * 128;
    int n0 = blockIdx.x * 128;
    int g = n0 >> 9;
    int nn0 = n0 & 511;
    const float* W    = (g == 0) ? Wi : (g == 1) ? Wf : (g == 2) ? Wo : Wc;
    const float* bias = (g == 0) ? bi : (g == 1) ? bf : (g == 2) ? bo : bc;

    float c[2][8][4];
#pragma unroll
    for (int i = 0; i < 2; i++)
#pragma unroll
        for (int j = 0; j < 8; j++)
#pragma unroll
            for (int q = 0; q < 4; q++) c[i][j][q] = 0.f;

    int arow[2], ac4[2], bk[2], bnq[2];
#pragma unroll
    for (int u = 0; u < 2; u++) {
        int ci = tid + u * 256;
        arow[u] = ci >> 2;  ac4[u] = ci & 3;
        bk[u]   = ci >> 5;  bnq[u] = ci & 31;
    }

    float4 pa[2], pb[2];
#pragma unroll
    for (int u = 0; u < 2; u++) {
        pa[u] = *(const float4*)(x + (size_t)(m0 + arow[u]) * DIN + ac4[u] * 4);
        pb[u] = *(const float4*)(W + (size_t)bk[u] * DH + nn0 + bnq[u] * 4);
    }

    for (int kt = 0; kt < DIN; kt += 16) {
        __syncthreads();
#pragma unroll
        for (int u = 0; u < 2; u++) {
            unsigned* pA = &As[arow[u] * ASTRIDE + ac4[u] * 4];
            pA[0] = tf32cvt(pa[u].x); pA[1] = tf32cvt(pa[u].y);
            pA[2] = tf32cvt(pa[u].z); pA[3] = tf32cvt(pa[u].w);
            unsigned* pB = &Bs[bk[u] * BSTRIDE + bnq[u] * 4];
            pB[0] = tf32cvt(pb[u].x); pB[1] = tf32cvt(pb[u].y);
            pB[2] = tf32cvt(pb[u].z); pB[3] = tf32cvt(pb[u].w);
        }
        __syncthreads();
        if (kt + 16 < DIN) {
#pragma unroll
            for (int u = 0; u < 2; u++) {
                pa[u] = *(const float4*)(x + (size_t)(m0 + arow[u]) * DIN + kt + 16 + ac4[u] * 4);
                pb[u] = *(const float4*)(W + (size_t)(kt + 16 + bk[u]) * DH + nn0 + bnq[u] * 4);
            }
        }
#pragma unroll
        for (int kk = 0; kk < 16; kk += 8) {
            unsigned a[2][4], b[8][2];
#pragma unroll
            for (int mf = 0; mf < 2; mf++) {
                int rb = wm * 32 + mf * 16 + grp;
                a[mf][0] = As[rb * ASTRIDE + kk + tg];
                a[mf][1] = As[(rb + 8) * ASTRIDE + kk + tg];
                a[mf][2] = As[rb * ASTRIDE + kk + tg + 4];
                a[mf][3] = As[(rb + 8) * ASTRIDE + kk + tg + 4];
            }
#pragma unroll
            for (int nf = 0; nf < 8; nf++) {
                int cb = wn * 64 + nf * 8 + grp;
                b[nf][0] = Bs[(kk + tg) * BSTRIDE + cb];
                b[nf][1] = Bs[(kk + tg + 4) * BSTRIDE + cb];
            }
#pragma unroll
            for (int mf = 0; mf < 2; mf++)
#pragma unroll
                for (int nf = 0; nf < 8; nf++) {
                    asm volatile(
                        "mma.sync.aligned.m16n8k8.row.col.f32.tf32.tf32.f32 "
                        "{%0,%1,%2,%3}, {%4,%5,%6,%7}, {%8,%9}, {%0,%1,%2,%3};"
                        : "+f"(c[mf][nf][0]), "+f"(c[mf][nf][1]),
                          "+f"(c[mf][nf][2]), "+f"(c[mf][nf][3])
                        : "r"(a[mf][0]), "r"(a[mf][1]), "r"(a[mf][2]), "r"(a[mf][3]),
                          "r"(b[nf][0]), "r"(b[nf][1]));
                }
        }
    }

#pragma unroll
    for (int mf = 0; mf < 2; mf++) {
        int row0 = m0 + wm * 32 + mf * 16 + grp;
#pragma unroll
        for (int nf = 0; nf < 8; nf++) {
            int h = nn0 + wn * 64 + nf * 8 + tg * 2;
            float2 bb = *(const float2*)(bias + h);
            {
                int b = row0 >> 10, t = row0 & 1023;
                float2 v = make_float2(c[mf][nf][0] + bb.x, c[mf][nf][1] + bb.y);
                *(float2*)(g_gates + ((size_t)(t * BATCH + b) * 4 + g) * DH + h) = v;
            }
            {
                int r1 = row0 + 8;
                int b = r1 >> 10, t = r1 & 1023;
                float2 v = make_float2(c[mf][nf][2] + bb.x, c[mf][nf][3] + bb.y);
                *(float2*)(g_gates + ((size_t)(t * BATCH + b) * 4 + g) * DH + h) = v;
            }
        }
    }
}

// ---------------- phase 2: persistent recurrence, tensor-core ---------------
// EXACT R14 structure (measured best): per-CTA flags, upfront spread poll,
// two bar.syncs, one release store, rcp.approx epilogue.
#define STEP_THREADS 512
#define RS 24
#define SMEM_STEPS (16 * 32 * RS * 4)

#define MMA_T(C, A, B)                                                          \
    asm volatile(                                                               \
        "mma.sync.aligned.m16n8k8.row.col.f32.tf32.tf32.f32 "                   \
        "{%0,%1,%2,%3}, {%4,%5,%6,%7}, {%8,%9}, {%0,%1,%2,%3};"                 \
        : "+f"(C[0]), "+f"(C[1]), "+f"(C[2]), "+f"(C[3])                        \
        : "r"(A[0]), "r"(A[1]), "r"(A[2]), "r"(A[3]), "r"(B[0]), "r"(B[1]));

__global__ __launch_bounds__(STEP_THREADS, 1) void k_steps(float* __restrict__ out) {
    extern __shared__ float red[];   // [ws][m(32)][RS], n in [0,16)

    int tid = threadIdx.x;
    int lane = tid & 31;
    int ws = tid >> 5;
    int grp = lane >> 2, tg = lane & 3;
    int bx = blockIdx.x;

    // ---- precompute W fragments (big + small), resident all steps ----------
    unsigned wb[2][4][2], wsm[2][4][2];
#pragma unroll
    for (int nt = 0; nt < 2; nt++) {
        int n = nt * 8 + grp;
        int g = n >> 2, h2 = n & 3;
        const float* wrow = g_Wt + (size_t)g * DH * DH + (size_t)(bx * 4 + h2) * DH;
#pragma unroll
        for (int q = 0; q < 4; q++) {
            int k0 = 32 * ws + 8 * q + tg;
#pragma unroll
            for (int u = 0; u < 2; u++) {
                float w = wrow[k0 + u * 4];
                unsigned b = tf32cvt(w);
                wb[nt][q][u] = b;
                wsm[nt][q][u] = tf32cvt(w - __uint_as_float(b));
            }
        }
    }

    // every lane polls one of this warp's 8 producer flags (CTAs 8*ws..8*ws+7)
    const unsigned* myflag = &g_flags[(ws * 8 + (lane & 7)) * 32];

    // per-thread reduction/epilogue identity: (m, n)
    int m_r = tid >> 4;
    int n_r = tid & 15;
    const float* gsrc = g_gates + ((size_t)m_r * 4 + (n_r >> 2)) * DH + bx * 4 + (n_r & 3);

    // leader (n_r < 4) H-write index in fragment layout
    int hg_e = bx * 4 + n_r;                 // n_r = h2 for leaders
    int mtE = m_r >> 4, mmE = m_r & 15;
    int grpE = mmE & 7, mhighE = mmE >> 3;
    int K8E = hg_e >> 3, kkE = hg_e & 7;
    int tgE = kkE & 3, khighE = kkE >> 2;
    int idxE = (((K8E * 2 + mtE) * 32) + grpE * 4 + tgE) * 4 + (khighE * 2 + mhighE);
    float Creg = 0.f;

    for (int t = 0; t < SEQ; t++) {
        // ---- prefetch this thread's gate pre-activation (DRAM, overlaps wait)
        float gv = __ldg(gsrc + (size_t)t * BATCH * 4 * DH);

        // ---- wait for this warp's 8 producers (skip t=0: H0 preset to 0) ----
        if (t > 0) {
            unsigned target = (unsigned)t;
            unsigned v;
            do {
                asm volatile("ld.acquire.gpu.global.u32 %0, [%1];"
                             : "=r"(v) : "l"(myflag) : "memory");
            } while (v < target);
            __syncwarp();
        }

        // ---- tensor-core compute: C[2][2][4] over K=32, pre-split H --------
        const float* Hb = g_H[t & 1][0];
        const float* Hs = g_H[t & 1][1];
        float c[2][2][4];
#pragma unroll
        for (int i = 0; i < 2; i++)
#pragma unroll
            for (int j = 0; j < 2; j++)
#pragma unroll
                for (int q = 0; q < 4; q++) c[i][j][q] = 0.f;

#pragma unroll
        for (int q = 0; q < 4; q++) {
            int K8 = ws * 4 + q;
#pragma unroll
            for (int mt = 0; mt < 2; mt++) {
                size_t off = ((size_t)(K8 * 2 + mt) * 32 + lane) * 4;
                unsigned ab[4], as_[4];
                asm("ld.global.cg.v4.b32 {%0,%1,%2,%3}, [%4];"
                    : "=r"(ab[0]), "=r"(ab[1]), "=r"(ab[2]), "=r"(ab[3])
                    : "l"(Hb + off));
                asm("ld.global.cg.v4.b32 {%0,%1,%2,%3}, [%4];"
                    : "=r"(as_[0]), "=r"(as_[1]), "=r"(as_[2]), "=r"(as_[3])
                    : "l"(Hs + off));
#pragma unroll
                for (int nt = 0; nt < 2; nt++) {
                    MMA_T(c[mt][nt], ab,  wb[nt][q]);
                    MMA_T(c[mt][nt], ab,  wsm[nt][q]);
                    MMA_T(c[mt][nt], as_, wb[nt][q]);
                }
            }
        }

        // ---- store partials to red[ws][m][n] ----
#pragma unroll
        for (int mt = 0; mt < 2; mt++)
#pragma unroll
            for (int nt = 0; nt < 2; nt++) {
                float* r0 = &red[((ws * 32) + 16 * mt + grp) * RS + nt * 8 + 2 * tg];
                *(float2*)r0            = make_float2(c[mt][nt][0], c[mt][nt][1]);
                *(float2*)(r0 + 8 * RS) = make_float2(c[mt][nt][2], c[mt][nt][3]);
            }
        __syncthreads();

        // ---- 16-way k-split reduction (all 512 threads, one (m,n) each) ----
        float s0 = gv, s1 = 0.f, s2 = 0.f, s3 = 0.f;
        {
            const float* rp = &red[m_r * RS + n_r];
#pragma unroll
            for (int w4 = 0; w4 < 4; w4++) {
                s0 += rp[(w4 * 4 + 0) * 32 * RS];
                s1 += rp[(w4 * 4 + 1) * 32 * RS];
                s2 += rp[(w4 * 4 + 2) * 32 * RS];
                s3 += rp[(w4 * 4 + 3) * 32 * RS];
            }
        }
        float s = (s0 + s1) + (s2 + s3);

        // gather the 4 gate sums to leaders (n_r < 4) via shfl
        float v1 = __shfl_sync(0xffffffffu, s, lane + 4);
        float v2 = __shfl_sync(0xffffffffu, s, lane + 8);
        float v3 = __shfl_sync(0xffffffffu, s, lane + 12);

        float Hn = 0.f;
        if (n_r < 4) {
            float I  = frcp(1.f + __expf(-s));
            float F  = frcp(1.f + __expf(-v1));
            float O  = frcp(1.f + __expf(-v2));
            float e2 = __expf(2.f * v3);
            float Cc = 1.f - 2.f * frcp(e2 + 1.f);     // tanh

            Creg = F * Creg + I * Cc;
            float ec = __expf(2.f * Creg);
            Hn = O * (1.f - 2.f * frcp(ec + 1.f));

            // pre-split store for next step's consumers
            unsigned hb = tf32cvt(Hn);
            float hbf = __uint_as_float(hb);
            float hsf = __uint_as_float(tf32cvt(Hn - hbf));
            int p = (t + 1) & 1;
            __stcg(&g_H[p][0][idxE], hbf);
            __stcg(&g_H[p][1][idxE], hsf);
        }
        __syncthreads();

        // ---- publish: release store of this CTA's flag ----
        if (tid == 0) {
            asm volatile("st.release.gpu.global.u32 [%0], %1;"
                         :: "l"(&g_flags[bx * 32]), "r"((unsigned)(t + 1)) : "memory");
        }
        if (n_r < 4)
            out[((size_t)m_r * SEQ + t) * DH + hg_e] = Hn;
    }
}

// ---------------- final H copy ---------------------------------------------
__global__ void k_final(float* __restrict__ out) {
    int i = blockIdx.x * blockDim.x + threadIdx.x;
    if (i < BATCH * DH) {
        int m = i >> 9, h = i & 511;
        int mt = m >> 4, mm = m & 15;
        int grp = mm & 7, mhigh = mm >> 3;
        int K8 = h >> 3, kk = h & 7;
        int tg = kk & 3, khigh = kk >> 2;
        int idx = (((K8 * 2 + mt) * 32) + grp * 4 + tg) * 4 + (khigh * 2 + mhigh);
        out[(size_t)BATCH * SEQ * DH + i] = g_H[0][0][idx] + g_H[0][1][idx];
    }
}

// ---------------- launch ----------------------------------------------------
extern "C" void kernel_launch(void* const* d_in, const int* in_sizes, int n_in,
                              void* d_out, int out_size) {
    const float* x   = (const float*)d_in[0];
    const float* Wxi = (const float*)d_in[1];
    const float* Whi = (const float*)d_in[2];
    const float* bi  = (const float*)d_in[3];
    const float* Wxf = (const float*)d_in[4];
    const float* Whf = (const float*)d_in[5];
    const float* bf  = (const float*)d_in[6];
    const float* Wxo = (const float*)d_in[7];
    const float* Who = (const float*)d_in[8];
    const float* bo  = (const float*)d_in[9];
    const float* Wxc = (const float*)d_in[10];
    const float* Whc = (const float*)d_in[11];
    const float* bc  = (const float*)d_in[12];
    float* out = (float*)d_out;

    static int smem_set = 0;
    if (!smem_set) {
        cudaFuncSetAttribute(k_steps, cudaFuncAttributeMaxDynamicSharedMemorySize, SMEM_STEPS);
        smem_set = 1;
    }

    k_init<<<256, 256>>>();
    k_transpose<<<dim3(16, 16, 4), dim3(32, 8)>>>(Whi, Whf, Who, Whc);
    k_xproj<<<dim3(2048 / 128, 32768 / 128), 256>>>(x, Wxi, Wxf, Wxo, Wxc, bi, bf, bo, bc);
    k_steps<<<NCTA, STEP_THREADS, SMEM_STEPS>>>(out);
    k_final<<<64, 256>>>(out);
}

// round 17
// speedup vs baseline: 1.2014x; 1.1071x over previous
#include <cuda_runtime.h>
#include <cuda_bf16.h>

#define SEQ   1024
#define BATCH 32
#define DH    512
#define DIN   512
#define NCTA  128

typedef unsigned long long ull;

// ---------------- scratch (device globals; no allocations allowed) ----------
__device__ float g_gates[(size_t)SEQ * BATCH * 4 * DH]; // [t][b][g][h]
__device__ float g_Wt[4 * DH * DH];                     // [g][h][k] transposed recurrent weights
// H ping-pong, split-bf16, packed in m16n8k16 A-fragment layout:
//   [pingpong][hi/lo][ ((K16*2+mt)*32 + lane)*4 + reg ]  (bf16x2 per unsigned)
__device__ unsigned g_Hp[2][2][8192];
__device__ unsigned g_flags[NCTA * 32];                 // per-CTA step flags, 128B apart

__device__ __forceinline__ unsigned tf32cvt(float x) {
    unsigned u;
    asm("cvt.rna.tf32.f32 %0, %1;" : "=r"(u) : "f"(x));
    return u;
}

__device__ __forceinline__ float frcp(float x) {
    float r;
    asm("rcp.approx.f32 %0, %1;" : "=f"(r) : "f"(x));
    return r;
}

// ---------------- init ------------------------------------------------------
__global__ void k_init() {
    int i = blockIdx.x * blockDim.x + threadIdx.x;
    if (i < NCTA * 32) g_flags[i] = 0;
    if (i < 2 * 2 * 8192) ((unsigned*)g_Hp)[i] = 0;      // bf16 zero = 0 bits
}

// ---------------- transpose recurrent weights:  Wt[g][h][k] = Wh_g[k][h] ----
__global__ void k_transpose(const float* __restrict__ W0, const float* __restrict__ W1,
                            const float* __restrict__ W2, const float* __restrict__ W3) {
    __shared__ float tile[32][33];
    int gz = blockIdx.z;
    const float* W = (gz == 0) ? W0 : (gz == 1) ? W1 : (gz == 2) ? W2 : W3;
    int h0 = blockIdx.x * 32;
    int k0 = blockIdx.y * 32;
    for (int r = threadIdx.y; r < 32; r += 8)
        tile[r][threadIdx.x] = W[(size_t)(k0 + r) * DH + h0 + threadIdx.x];
    __syncthreads();
    float* out = g_Wt + (size_t)gz * DH * DH;
    for (int r = threadIdx.y; r < 32; r += 8)
        out[(size_t)(h0 + r) * DH + k0 + threadIdx.x] = tile[threadIdx.x][r];
}

// ---------------- phase 1: input projections, tf32 tensor-core GEMM ---------
#define ASTRIDE 20
#define BSTRIDE 136

__global__ __launch_bounds__(256, 2) void k_xproj(
    const float* __restrict__ x,
    const float* __restrict__ Wi, const float* __restrict__ Wf,
    const float* __restrict__ Wo, const float* __restrict__ Wc,
    const float* __restrict__ bi, const float* __restrict__ bf,
    const float* __restrict__ bo, const float* __restrict__ bc)
{
    __shared__ unsigned As[128 * ASTRIDE];
    __shared__ unsigned Bs[16 * BSTRIDE];

    int tid = threadIdx.x;
    int warp = tid >> 5, lane = tid & 31;
    int wm = warp >> 1, wn = warp & 1;
    int grp = lane >> 2, tg = lane & 3;

    int m0 = blockIdx.y * 128;
    int n0 = blockIdx.x * 128;
    int g = n0 >> 9;
    int nn0 = n0 & 511;
    const float* W    = (g == 0) ? Wi : (g == 1) ? Wf : (g == 2) ? Wo : Wc;
    const float* bias = (g == 0) ? bi : (g == 1) ? bf : (g == 2) ? bo : bc;

    float c[2][8][4];
#pragma unroll
    for (int i = 0; i < 2; i++)
#pragma unroll
        for (int j = 0; j < 8; j++)
#pragma unroll
            for (int q = 0; q < 4; q++) c[i][j][q] = 0.f;

    int arow[2], ac4[2], bk[2], bnq[2];
#pragma unroll
    for (int u = 0; u < 2; u++) {
        int ci = tid + u * 256;
        arow[u] = ci >> 2;  ac4[u] = ci & 3;
        bk[u]   = ci >> 5;  bnq[u] = ci & 31;
    }

    float4 pa[2], pb[2];
#pragma unroll
    for (int u = 0; u < 2; u++) {
        pa[u] = *(const float4*)(x + (size_t)(m0 + arow[u]) * DIN + ac4[u] * 4);
        pb[u] = *(const float4*)(W + (size_t)bk[u] * DH + nn0 + bnq[u] * 4);
    }

    for (int kt = 0; kt < DIN; kt += 16) {
        __syncthreads();
#pragma unroll
        for (int u = 0; u < 2; u++) {
            unsigned* pA = &As[arow[u] * ASTRIDE + ac4[u] * 4];
            pA[0] = tf32cvt(pa[u].x); pA[1] = tf32cvt(pa[u].y);
            pA[2] = tf32cvt(pa[u].z); pA[3] = tf32cvt(pa[u].w);
            unsigned* pB = &Bs[bk[u] * BSTRIDE + bnq[u] * 4];
            pB[0] = tf32cvt(pb[u].x); pB[1] = tf32cvt(pb[u].y);
            pB[2] = tf32cvt(pb[u].z); pB[3] = tf32cvt(pb[u].w);
        }
        __syncthreads();
        if (kt + 16 < DIN) {
#pragma unroll
            for (int u = 0; u < 2; u++) {
                pa[u] = *(const float4*)(x + (size_t)(m0 + arow[u]) * DIN + kt + 16 + ac4[u] * 4);
                pb[u] = *(const float4*)(W + (size_t)(kt + 16 + bk[u]) * DH + nn0 + bnq[u] * 4);
            }
        }
#pragma unroll
        for (int kk = 0; kk < 16; kk += 8) {
            unsigned a[2][4], b[8][2];
#pragma unroll
            for (int mf = 0; mf < 2; mf++) {
                int rb = wm * 32 + mf * 16 + grp;
                a[mf][0] = As[rb * ASTRIDE + kk + tg];
                a[mf][1] = As[(rb + 8) * ASTRIDE + kk + tg];
                a[mf][2] = As[rb * ASTRIDE + kk + tg + 4];
                a[mf][3] = As[(rb + 8) * ASTRIDE + kk + tg + 4];
            }
#pragma unroll
            for (int nf = 0; nf < 8; nf++) {
                int cb = wn * 64 + nf * 8 + grp;
                b[nf][0] = Bs[(kk + tg) * BSTRIDE + cb];
                b[nf][1] = Bs[(kk + tg + 4) * BSTRIDE + cb];
            }
#pragma unroll
            for (int mf = 0; mf < 2; mf++)
#pragma unroll
                for (int nf = 0; nf < 8; nf++) {
                    asm volatile(
                        "mma.sync.aligned.m16n8k8.row.col.f32.tf32.tf32.f32 "
                        "{%0,%1,%2,%3}, {%4,%5,%6,%7}, {%8,%9}, {%0,%1,%2,%3};"
                        : "+f"(c[mf][nf][0]), "+f"(c[mf][nf][1]),
                          "+f"(c[mf][nf][2]), "+f"(c[mf][nf][3])
                        : "r"(a[mf][0]), "r"(a[mf][1]), "r"(a[mf][2]), "r"(a[mf][3]),
                          "r"(b[nf][0]), "r"(b[nf][1]));
                }
        }
    }

#pragma unroll
    for (int mf = 0; mf < 2; mf++) {
        int row0 = m0 + wm * 32 + mf * 16 + grp;
#pragma unroll
        for (int nf = 0; nf < 8; nf++) {
            int h = nn0 + wn * 64 + nf * 8 + tg * 2;
            float2 bb = *(const float2*)(bias + h);
            {
                int b = row0 >> 10, t = row0 & 1023;
                float2 v = make_float2(c[mf][nf][0] + bb.x, c[mf][nf][1] + bb.y);
                *(float2*)(g_gates + ((size_t)(t * BATCH + b) * 4 + g) * DH + h) = v;
            }
            {
                int r1 = row0 + 8;
                int b = r1 >> 10, t = r1 & 1023;
                float2 v = make_float2(c[mf][nf][2] + bb.x, c[mf][nf][3] + bb.y);
                *(float2*)(g_gates + ((size_t)(t * BATCH + b) * 4 + g) * DH + h) = v;
            }
        }
    }
}

// ---------------- phase 2: persistent recurrence, split-bf16 tensor-core ----
// R16 sync structure (measured best). H stored as packed bf16 hi/lo in
// m16n8k16 A-fragment layout -> HALF the L2 traffic, HALF the mma count.
#define STEP_THREADS 512
#define RS 24
#define SMEM_STEPS (16 * 32 * RS * 4)

#define MMA16(C, A, B)                                                          \
    asm volatile(                                                               \
        "mma.sync.aligned.m16n8k16.row.col.f32.bf16.bf16.f32 "                  \
        "{%0,%1,%2,%3}, {%4,%5,%6,%7}, {%8,%9}, {%0,%1,%2,%3};"                 \
        : "+f"(C[0]), "+f"(C[1]), "+f"(C[2]), "+f"(C[3])                        \
        : "r"(A[0]), "r"(A[1]), "r"(A[2]), "r"(A[3]), "r"(B[0]), "r"(B[1]));

__global__ __launch_bounds__(STEP_THREADS, 1) void k_steps(float* __restrict__ out) {
    extern __shared__ float red[];   // [ws][m(32)][RS], n in [0,16)

    int tid = threadIdx.x;
    int lane = tid & 31;
    int ws = tid >> 5;
    int grp = lane >> 2, tg = lane & 3;
    int bx = blockIdx.x;

    // ---- precompute split-bf16 W fragments, resident all steps -------------
    // B frag m16n8k16: reg r covers k = base + r*8 + {2tg, 2tg+1}, col grp
    unsigned wbh[2][2][2], wbl[2][2][2];   // [nt][kh][reg]
#pragma unroll
    for (int nt = 0; nt < 2; nt++) {
        int n = nt * 8 + grp;
        int g = n >> 2, h2 = n & 3;
        const float* wrow = g_Wt + (size_t)g * DH * DH + (size_t)(bx * 4 + h2) * DH;
#pragma unroll
        for (int kh = 0; kh < 2; kh++)
#pragma unroll
            for (int r = 0; r < 2; r++) {
                int k0 = 32 * ws + kh * 16 + r * 8 + 2 * tg;
                float w0 = wrow[k0], w1 = wrow[k0 + 1];
                __nv_bfloat16 h0 = __float2bfloat16_rn(w0);
                __nv_bfloat16 h1 = __float2bfloat16_rn(w1);
                __nv_bfloat16 l0 = __float2bfloat16_rn(w0 - __bfloat162float(h0));
                __nv_bfloat16 l1 = __float2bfloat16_rn(w1 - __bfloat162float(h1));
                wbh[nt][kh][r] = ((unsigned)__bfloat16_as_ushort(h1) << 16)
                                 | __bfloat16_as_ushort(h0);
                wbl[nt][kh][r] = ((unsigned)__bfloat16_as_ushort(l1) << 16)
                                 | __bfloat16_as_ushort(l0);
            }
    }

    // every lane polls one of this warp's 8 producer flags (CTAs 8*ws..8*ws+7)
    const unsigned* myflag = &g_flags[(ws * 8 + (lane & 7)) * 32];

    // per-thread reduction/epilogue identity: (m, n)
    int m_r = tid >> 4;
    int n_r = tid & 15;
    const float* gsrc = g_gates + ((size_t)m_r * 4 + (n_r >> 2)) * DH + bx * 4 + (n_r & 3);

    // leader (n_r < 4) H-write address in packed bf16 fragment layout
    int hg_e = bx * 4 + n_r;                 // n_r = h2 for leaders
    int mtE = m_r >> 4, mrowE = m_r & 15;
    int K16E = hg_e >> 4, kkE = hg_e & 15;
    int regE = (mrowE >> 3) + 2 * (kkE >> 3);
    int laneE = (mrowE & 7) * 4 + ((kkE & 7) >> 1);
    int halfE = kkE & 1;
    size_t byteoffE = (size_t)(((K16E * 2 + mtE) * 32 + laneE) * 4 + regE) * 4 + halfE * 2;
    unsigned short* hiE[2], * loE[2];
#pragma unroll
    for (int p = 0; p < 2; p++) {
        hiE[p] = (unsigned short*)((unsigned char*)&g_Hp[p][0][0] + byteoffE);
        loE[p] = (unsigned short*)((unsigned char*)&g_Hp[p][1][0] + byteoffE);
    }
    float Creg = 0.f;

    for (int t = 0; t < SEQ; t++) {
        // ---- prefetch this thread's gate pre-activation (DRAM, overlaps wait)
        float gv = __ldg(gsrc + (size_t)t * BATCH * 4 * DH);

        // ---- wait for this warp's 8 producers (skip t=0: H0 preset to 0) ----
        if (t > 0) {
            unsigned target = (unsigned)t;
            unsigned v;
            do {
                asm volatile("ld.acquire.gpu.global.u32 %0, [%1];"
                             : "=r"(v) : "l"(myflag) : "memory");
            } while (v < target);
            __syncwarp();
        }

        // ---- tensor-core compute: K=32 per warp, split-bf16, 24 mma --------
        const unsigned* Hb = g_Hp[t & 1][0];
        const unsigned* Hs = g_Hp[t & 1][1];
        float c[2][2][4];
#pragma unroll
        for (int i = 0; i < 2; i++)
#pragma unroll
            for (int j = 0; j < 2; j++)
#pragma unroll
                for (int q = 0; q < 4; q++) c[i][j][q] = 0.f;

#pragma unroll
        for (int kh = 0; kh < 2; kh++) {
            int K16 = ws * 2 + kh;
#pragma unroll
            for (int mt = 0; mt < 2; mt++) {
                int off = ((K16 * 2 + mt) * 32 + lane) * 4;
                unsigned ah[4], al[4];
                asm("ld.global.cg.v4.b32 {%0,%1,%2,%3}, [%4];"
                    : "=r"(ah[0]), "=r"(ah[1]), "=r"(ah[2]), "=r"(ah[3])
                    : "l"(Hb + off));
                asm("ld.global.cg.v4.b32 {%0,%1,%2,%3}, [%4];"
                    : "=r"(al[0]), "=r"(al[1]), "=r"(al[2]), "=r"(al[3])
                    : "l"(Hs + off));
#pragma unroll
                for (int nt = 0; nt < 2; nt++) {
                    MMA16(c[mt][nt], ah, wbh[nt][kh]);
                    MMA16(c[mt][nt], ah, wbl[nt][kh]);
                    MMA16(c[mt][nt], al, wbh[nt][kh]);
                }
            }
        }

        // ---- store partials to red[ws][m][n] ----
#pragma unroll
        for (int mt = 0; mt < 2; mt++)
#pragma unroll
            for (int nt = 0; nt < 2; nt++) {
                float* r0 = &red[((ws * 32) + 16 * mt + grp) * RS + nt * 8 + 2 * tg];
                *(float2*)r0            = make_float2(c[mt][nt][0], c[mt][nt][1]);
                *(float2*)(r0 + 8 * RS) = make_float2(c[mt][nt][2], c[mt][nt][3]);
            }
        __syncthreads();

        // ---- 16-way k-split reduction (all 512 threads, one (m,n) each) ----
        float s0 = gv, s1 = 0.f, s2 = 0.f, s3 = 0.f;
        {
            const float* rp = &red[m_r * RS + n_r];
#pragma unroll
            for (int w4 = 0; w4 < 4; w4++) {
                s0 += rp[(w4 * 4 + 0) * 32 * RS];
                s1 += rp[(w4 * 4 + 1) * 32 * RS];
                s2 += rp[(w4 * 4 + 2) * 32 * RS];
                s3 += rp[(w4 * 4 + 3) * 32 * RS];
            }
        }
        float s = (s0 + s1) + (s2 + s3);

        // gather the 4 gate sums to leaders (n_r < 4) via shfl
        float v1 = __shfl_sync(0xffffffffu, s, lane + 4);
        float v2 = __shfl_sync(0xffffffffu, s, lane + 8);
        float v3 = __shfl_sync(0xffffffffu, s, lane + 12);

        float Hn = 0.f;
        if (n_r < 4) {
            float I  = frcp(1.f + __expf(-s));
            float F  = frcp(1.f + __expf(-v1));
            float O  = frcp(1.f + __expf(-v2));
            float e2 = __expf(2.f * v3);
            float Cc = 1.f - 2.f * frcp(e2 + 1.f);     // tanh

            Creg = F * Creg + I * Cc;
            float ec = __expf(2.f * Creg);
            Hn = O * (1.f - 2.f * frcp(ec + 1.f));

            // split-bf16 store for next step's consumers
            __nv_bfloat16 bh = __float2bfloat16_rn(Hn);
            float fh = __bfloat162float(bh);
            __nv_bfloat16 bl = __float2bfloat16_rn(Hn - fh);
            unsigned short uh = __bfloat16_as_ushort(bh);
            unsigned short ul = __bfloat16_as_ushort(bl);
            int p = (t + 1) & 1;
            asm volatile("st.global.cg.u16 [%0], %1;" :: "l"(hiE[p]), "h"(uh) : "memory");
            asm volatile("st.global.cg.u16 [%0], %1;" :: "l"(loE[p]), "h"(ul) : "memory");
        }
        __syncthreads();

        // ---- publish: release store of this CTA's flag ----
        if (tid == 0) {
            asm volatile("st.release.gpu.global.u32 [%0], %1;"
                         :: "l"(&g_flags[bx * 32]), "r"((unsigned)(t + 1)) : "memory");
        }
        if (n_r < 4)
            out[((size_t)m_r * SEQ + t) * DH + hg_e] = Hn;
    }
}

// ---------------- final H copy ---------------------------------------------
__global__ void k_final(float* __restrict__ out) {
    int i = blockIdx.x * blockDim.x + threadIdx.x;
    if (i < BATCH * DH) {
        int m = i >> 9, h = i & 511;
        int mt = m >> 4, mrow = m & 15;
        int K16 = h >> 4, kk = h & 15;
        int reg = (mrow >> 3) + 2 * (kk >> 3);
        int lane2 = (mrow & 7) * 4 + ((kk & 7) >> 1);
        int half = kk & 1;
        int uidx = ((K16 * 2 + mt) * 32 + lane2) * 4 + reg;
        unsigned short uh = ((const unsigned short*)&g_Hp[0][0][0])[uidx * 2 + half];
        unsigned short ul = ((const unsigned short*)&g_Hp[0][1][0])[uidx * 2 + half];
        out[(size_t)BATCH * SEQ * DH + i] =
            __bfloat162float(__ushort_as_bfloat16(uh)) +
            __bfloat162float(__ushort_as_bfloat16(ul));
    }
}

// ---------------- launch ----------------------------------------------------
extern "C" void kernel_launch(void* const* d_in, const int* in_sizes, int n_in,
                              void* d_out, int out_size) {
    const float* x   = (const float*)d_in[0];
    const float* Wxi = (const float*)d_in[1];
    const float* Whi = (const float*)d_in[2];
    const float* bi  = (const float*)d_in[3];
    const float* Wxf = (const float*)d_in[4];
    const float* Whf = (const float*)d_in[5];
    const float* bf  = (const float*)d_in[6];
    const float* Wxo = (const float*)d_in[7];
    const float* Who = (const float*)d_in[8];
    const float* bo  = (const float*)d_in[9];
    const float* Wxc = (const float*)d_in[10];
    const float* Whc = (const float*)d_in[11];
    const float* bc  = (const float*)d_in[12];
    float* out = (float*)d_out;

    static int smem_set = 0;
    if (!smem_set) {
        cudaFuncSetAttribute(k_steps, cudaFuncAttributeMaxDynamicSharedMemorySize, SMEM_STEPS);
        smem_set = 1;
    }

    k_init<<<256, 256>>>();
    k_transpose<<<dim3(16, 16, 4), dim3(32, 8)>>>(Whi, Whf, Who, Whc);
    k_xproj<<<dim3(2048 / 128, 32768 / 128), 256>>>(x, Wxi, Wxf, Wxo, Wxc, bi, bf, bo, bc);
    k_steps<<<NCTA, STEP_THREADS, SMEM_STEPS>>>(out);
    k_final<<<64, 256>>>(out);
}